// round 3
// baseline (speedup 1.0000x reference)
#include <cuda_runtime.h>
#include <math.h>

#define B_  64
#define T_  256
#define D_  1024
#define H_  1024
#define G4  4096
#define NBLK 128
#define HS  65        // u64 stride per-kk in duplicated h smem (pad vs bank conflicts)

typedef unsigned long long u64;

__device__ __forceinline__ u64 ffma2(u64 a, u64 b, u64 c) {
    u64 d; asm("fma.rn.f32x2 %0, %1, %2, %3;" : "=l"(d) : "l"(a), "l"(b), "l"(c));
    return d;
}
__device__ __forceinline__ u64 pack2(float x, float y) {
    u64 d; asm("mov.b64 %0, {%1, %2};" : "=l"(d) : "f"(x), "f"(y));
    return d;
}
__device__ __forceinline__ float2 unpack2(u64 v) {
    float2 f; asm("mov.b64 {%0, %1}, %2;" : "=f"(f.x), "=f"(f.y) : "l"(v));
    return f;
}
__device__ __forceinline__ float sigf(float x) {
    return 1.f / (1.f + __expf(-x));
}
__device__ __forceinline__ float tanhfast(float x) {
    return 2.f * sigf(2.f * x) - 1.f;
}

// ---- scratch ----
__device__ float g_gx[(size_t)T_ * B_ * G4];     // [T][B][4H]
__device__ float g_hs[(size_t)B_ * T_ * H_];     // [B][T][H]
__device__ float g_hbuf[2][B_ * H_];
__device__ float g_cbuf[B_ * H_];

__device__ unsigned g_bar_count = 0;
__device__ unsigned g_bar_gen   = 0;

// ============================================================
// SGEMM 128x128x8 with packed f32x2 FFMA2. 256 threads, 8x8 microtile
// (stored as 8 x 4 u64 accumulators, columns packed in pairs).
// A staged in smem PRE-DUPLICATED ({a,a} u64), B staged as plain floats.
// ============================================================
template<bool REMAP>
__global__ __launch_bounds__(256) void sgemm128_f2(
    const float* __restrict__ A, const float* __restrict__ Bm,
    const float* __restrict__ bias, float* __restrict__ C, int ldc)
{
    const int K = 1024;
    __shared__ u64   Asd[8][128];   // [k][m] duplicated
    __shared__ float Bs[8][128];    // [k][n]

    int tid = threadIdx.x;
    int tx  = tid & 15;
    int ty  = tid >> 4;
    int m0  = blockIdx.y * 128;
    int n0  = blockIdx.x * 128;

    u64 acc[8][4];
    #pragma unroll
    for (int i = 0; i < 8; i++)
        #pragma unroll
        for (int j = 0; j < 4; j++) acc[i][j] = 0ull;

    int a_row  = tid >> 1;
    int a_col4 = (tid & 1) * 4;
    int b_row  = tid >> 5;
    int b_col4 = (tid & 31) * 4;

    const float* Ag = A  + (size_t)(m0 + a_row) * K + a_col4;
    const float* Bg = Bm + (size_t)b_row * 1024 + n0 + b_col4;

    for (int k0 = 0; k0 < K; k0 += 8) {
        float4 av = *(const float4*)(Ag + k0);
        float4 bv = *(const float4*)(Bg + (size_t)k0 * 1024);
        __syncthreads();
        Asd[a_col4 + 0][a_row] = pack2(av.x, av.x);
        Asd[a_col4 + 1][a_row] = pack2(av.y, av.y);
        Asd[a_col4 + 2][a_row] = pack2(av.z, av.z);
        Asd[a_col4 + 3][a_row] = pack2(av.w, av.w);
        *(float4*)&Bs[b_row][b_col4] = bv;
        __syncthreads();

        #pragma unroll
        for (int kk = 0; kk < 8; kk++) {
            u64 ar[8];
            #pragma unroll
            for (int r = 0; r < 4; r++) {
                ulonglong2 v = *(const ulonglong2*)&Asd[kk][ty * 8 + r * 2];
                ar[r * 2] = v.x; ar[r * 2 + 1] = v.y;
            }
            ulonglong2 b01 = *(const ulonglong2*)&Bs[kk][tx * 8];
            ulonglong2 b23 = *(const ulonglong2*)&Bs[kk][tx * 8 + 4];
            u64 br[4] = {b01.x, b01.y, b23.x, b23.y};
            #pragma unroll
            for (int i = 0; i < 8; i++)
                #pragma unroll
                for (int j = 0; j < 4; j++)
                    acc[i][j] = ffma2(ar[i], br[j], acc[i][j]);
        }
    }

    #pragma unroll
    for (int i = 0; i < 8; i++) {
        int r = m0 + ty * 8 + i;
        size_t rowoff;
        if (REMAP) {
            int b = r >> 8;
            int t = r & 255;
            rowoff = ((size_t)t * B_ + b) * (size_t)ldc;
        } else {
            rowoff = (size_t)r * (size_t)ldc;
        }
        #pragma unroll
        for (int jq = 0; jq < 2; jq++) {
            float2 p0 = unpack2(acc[i][jq * 2]);
            float2 p1 = unpack2(acc[i][jq * 2 + 1]);
            int col = n0 + tx * 8 + jq * 4;
            float4 v;
            v.x = p0.x + bias[col + 0];
            v.y = p0.y + bias[col + 1];
            v.z = p1.x + bias[col + 2];
            v.w = p1.y + bias[col + 3];
            *(float4*)(C + rowoff + col) = v;
        }
    }
}

// ============================================================
// grid barrier (all 128 blocks co-resident, 1/SM)
// ============================================================
__device__ __forceinline__ void grid_sync_128(int tid)
{
    __syncthreads();
    if (tid == 0) {
        unsigned gen = *(volatile unsigned*)&g_bar_gen;
        __threadfence();
        if (atomicAdd(&g_bar_count, 1u) == NBLK - 1) {
            g_bar_count = 0;
            __threadfence();
            atomicExch(&g_bar_gen, gen + 1u);
        } else {
            while (*(volatile unsigned*)&g_bar_gen == gen) { __nanosleep(64); }
            __threadfence();
        }
    }
    __syncthreads();
}

// ============================================================
// Persistent LSTM recurrence, f32x2 inner loop.
// 128 blocks x 256 threads. Block owns 8 h-columns (all gates, all rows).
// Thread tile: 2 rows x 2 cols x 2 gates (gate-split across thread halves).
// U slice (128 KB) staged once; h staged per 64-k chunk PRE-DUPLICATED u64,
// double-buffered. Cell state c held in registers across all 256 steps.
// smem: su 128KB + shd 65KB + sg 8KB = 201KB -> 1 block/SM.
// ============================================================
extern "C" __global__ void __launch_bounds__(256, 1) lstm_persistent(
    const float* __restrict__ Ui, const float* __restrict__ Uf,
    const float* __restrict__ Uj, const float* __restrict__ Uo)
{
    extern __shared__ float smem[];
    float* su  = smem;                           // [4][1024][8] floats
    u64*   shd = (u64*)(smem + 4 * 1024 * 8);    // [2][64*HS] u64 (dup h)
    float* sg  = (float*)(shd + 2 * 64 * HS);    // [4][64][8] gate exchange

    const int tid = threadIdx.x;
    const int n0  = blockIdx.x * 8;
    const int gh  = tid >> 7;                    // gate half: 0 -> i,f ; 1 -> j,o
    const int g0  = gh * 2;
    const int rg  = (tid & 127) >> 2;            // 0..31
    const int cg  = tid & 3;                     // col pair
    const int row0 = 2 * rg, row1 = row0 + 1;
    const int rowE = row0 + gh;                  // epilogue cell row
    const int nc   = n0 + 2 * cg;                // first of 2 owned cols

    // ---- stage U once ----
    const float* Uptr[4] = {Ui, Uf, Uj, Uo};
    for (int i = 0; i < 128; i++) {
        int idx = i * 256 + tid;                 // 0..32767
        int g   = idx >> 13;
        int k   = (idx >> 3) & 1023;
        int c   = idx & 7;
        su[idx] = Uptr[g][(size_t)k * 1024 + n0 + c];
    }

    // ---- cell state in registers ----
    float2 creg = *(const float2*)(g_cbuf + rowE * H_ + nc);
    __syncthreads();

    const float* sup0 = su + g0 * 8192 + 2 * cg;
    const float* sup1 = sup0 + 8192;

    for (int t = 0; t < T_; t++) {
        const float* hprev = g_hbuf[t & 1];
        float*       hnext = g_hbuf[(t + 1) & 1];

        // prefetch gx for this thread's 2 cells (used at epilogue)
        const float* gxp = g_gx + (size_t)t * B_ * G4 + (size_t)rowE * G4 + nc;
        float2 gxi = *(const float2*)(gxp);
        float2 gxf = *(const float2*)(gxp + 1024);
        float2 gxj = *(const float2*)(gxp + 2048);
        float2 gxo = *(const float2*)(gxp + 3072);

        u64 acc00 = 0, acc01 = 0, acc10 = 0, acc11 = 0;

        // prefetch chunk 0 (4 float4/thread) and store duplicated
        float4 pf[4];
        #pragma unroll
        for (int i = 0; i < 4; i++) {
            int f4  = i * 256 + tid;             // 0..1023
            int row = f4 >> 4;                   // 0..63
            int kq  = f4 & 15;
            pf[i] = *(const float4*)(hprev + (size_t)row * H_ + kq * 4);
        }
        #pragma unroll
        for (int i = 0; i < 4; i++) {
            int f4  = i * 256 + tid;
            int row = f4 >> 4;
            int kq  = f4 & 15;
            u64* d = shd + (size_t)(kq * 4) * HS + row;
            d[0 * HS] = pack2(pf[i].x, pf[i].x);
            d[1 * HS] = pack2(pf[i].y, pf[i].y);
            d[2 * HS] = pack2(pf[i].z, pf[i].z);
            d[3 * HS] = pack2(pf[i].w, pf[i].w);
        }
        __syncthreads();

        for (int cch = 0; cch < 16; cch++) {
            // prefetch next chunk
            if (cch < 15) {
                int k0 = (cch + 1) * 64;
                #pragma unroll
                for (int i = 0; i < 4; i++) {
                    int f4  = i * 256 + tid;
                    int row = f4 >> 4;
                    int kq  = f4 & 15;
                    pf[i] = *(const float4*)(hprev + (size_t)row * H_ + k0 + kq * 4);
                }
            }

            // compute on current buffer
            const u64*   hb = shd + (size_t)(cch & 1) * (64 * HS);
            const float* u0p = sup0 + (size_t)cch * 64 * 8;
            const float* u1p = sup1 + (size_t)cch * 64 * 8;
            #pragma unroll 16
            for (int kk = 0; kk < 64; kk++) {
                u64 h0 = hb[kk * HS + row0];
                u64 h1 = hb[kk * HS + row1];
                u64 u0 = *(const u64*)(u0p + kk * 8);
                u64 u1 = *(const u64*)(u1p + kk * 8);
                acc00 = ffma2(h0, u0, acc00);
                acc01 = ffma2(h1, u0, acc01);
                acc10 = ffma2(h0, u1, acc10);
                acc11 = ffma2(h1, u1, acc11);
            }

            // store next chunk into other buffer
            if (cch < 15) {
                u64* dst = shd + (size_t)((cch + 1) & 1) * (64 * HS);
                #pragma unroll
                for (int i = 0; i < 4; i++) {
                    int f4  = i * 256 + tid;
                    int row = f4 >> 4;
                    int kq  = f4 & 15;
                    u64* d = dst + (size_t)(kq * 4) * HS + row;
                    d[0 * HS] = pack2(pf[i].x, pf[i].x);
                    d[1 * HS] = pack2(pf[i].y, pf[i].y);
                    d[2 * HS] = pack2(pf[i].z, pf[i].z);
                    d[3 * HS] = pack2(pf[i].w, pf[i].w);
                }
            }
            __syncthreads();
        }

        // ---- gate exchange: write partials, recombine per cell ----
        *(u64*)&sg[(g0    ) * 512 + row0 * 8 + 2 * cg] = acc00;
        *(u64*)&sg[(g0    ) * 512 + row1 * 8 + 2 * cg] = acc01;
        *(u64*)&sg[(g0 + 1) * 512 + row0 * 8 + 2 * cg] = acc10;
        *(u64*)&sg[(g0 + 1) * 512 + row1 * 8 + 2 * cg] = acc11;
        __syncthreads();

        float2 pgi = *(const float2*)&sg[0 * 512 + rowE * 8 + 2 * cg];
        float2 pgf = *(const float2*)&sg[1 * 512 + rowE * 8 + 2 * cg];
        float2 pgj = *(const float2*)&sg[2 * 512 + rowE * 8 + 2 * cg];
        float2 pgo = *(const float2*)&sg[3 * 512 + rowE * 8 + 2 * cg];

        float2 hv;
        {
            float gi = pgi.x + gxi.x, gf = pgf.x + gxf.x;
            float gj = pgj.x + gxj.x, go = pgo.x + gxo.x;
            float iv = sigf(gi), fv = sigf(gf), jv = tanhfast(gj), ov = sigf(go);
            creg.x = fv * creg.x + iv * jv;
            hv.x = ov * tanhfast(creg.x);
        }
        {
            float gi = pgi.y + gxi.y, gf = pgf.y + gxf.y;
            float gj = pgj.y + gxj.y, go = pgo.y + gxo.y;
            float iv = sigf(gi), fv = sigf(gf), jv = tanhfast(gj), ov = sigf(go);
            creg.y = fv * creg.y + iv * jv;
            hv.y = ov * tanhfast(creg.y);
        }

        *(float2*)(hnext + rowE * H_ + nc) = hv;
        *(float2*)(g_hs + (size_t)rowE * T_ * H_ + (size_t)t * H_ + nc) = hv;

        grid_sync_128(tid);
    }
}

// ============================================================
// Inputs: x, h0, c0, W_i..W_o, U_i..U_o, b_i..b_o, W_y, b_y
// ============================================================
extern "C" void kernel_launch(void* const* d_in, const int* in_sizes, int n_in,
                              void* d_out, int out_size)
{
    const float* x  = (const float*)d_in[0];
    const float* h0 = (const float*)d_in[1];
    const float* c0 = (const float*)d_in[2];
    const float* W[4] = {(const float*)d_in[3], (const float*)d_in[4],
                         (const float*)d_in[5], (const float*)d_in[6]};
    const float* U[4] = {(const float*)d_in[7], (const float*)d_in[8],
                         (const float*)d_in[9], (const float*)d_in[10]};
    const float* bb[4] = {(const float*)d_in[11], (const float*)d_in[12],
                          (const float*)d_in[13], (const float*)d_in[14]};
    const float* Wy = (const float*)d_in[15];
    const float* by = (const float*)d_in[16];
    float* y = (float*)d_out;

    cudaMemcpyToSymbolAsync(g_hbuf, h0, (size_t)B_ * H_ * sizeof(float), 0,
                            cudaMemcpyDeviceToDevice, 0);
    cudaMemcpyToSymbolAsync(g_cbuf, c0, (size_t)B_ * H_ * sizeof(float), 0,
                            cudaMemcpyDeviceToDevice, 0);

    float* gx_ptr; cudaGetSymbolAddress((void**)&gx_ptr, g_gx);
    float* hs_ptr; cudaGetSymbolAddress((void**)&hs_ptr, g_hs);

    dim3 grid(8, 128);

    for (int g = 0; g < 4; g++)
        sgemm128_f2<true><<<grid, 256>>>(x, W[g], bb[g], gx_ptr + g * 1024, G4);

    const int smem_bytes = 4 * 1024 * 8 * sizeof(float)      // su 128KB
                         + 2 * 64 * HS * sizeof(u64)         // shd ~65KB
                         + 4 * 64 * 8 * sizeof(float);       // sg 8KB
    cudaFuncSetAttribute(lstm_persistent,
                         cudaFuncAttributeMaxDynamicSharedMemorySize, smem_bytes);
    lstm_persistent<<<NBLK, 256, smem_bytes>>>(U[0], U[1], U[2], U[3]);

    sgemm128_f2<false><<<grid, 256>>>(hs_ptr, Wy, by, y, 1024);
}

// round 4
// speedup vs baseline: 2.3428x; 2.3428x over previous
#include <cuda_runtime.h>
#include <math.h>

#define B_  64
#define T_  256
#define D_  1024
#define H_  1024
#define G4  4096
#define NBLK 128
#define KST 68      // k-row stride (floats) in transposed h smem chunk
#define RST 34      // row stride (floats) in reduction buffer
#define KGS 2176    // kg stride (floats) in reduction buffer (64*34)

// ---- scratch ----
__device__ float g_gx[(size_t)T_ * B_ * G4];     // [T][B][4H]
__device__ float g_hs[(size_t)B_ * T_ * H_];     // [B][T][H]
__device__ float g_hbuf[2][B_ * H_];
__device__ float g_cbuf[B_ * H_];

__device__ unsigned g_bar_count = 0;
__device__ unsigned g_bar_gen   = 0;

__device__ __forceinline__ float sigf(float x)   { return 1.f / (1.f + __expf(-x)); }
__device__ __forceinline__ float tanhfast(float x){ return 2.f * sigf(2.f * x) - 1.f; }

// ============================================================
// SGEMM 128x128x8, 8x8 microtile, 256 threads (R1 proven version).
// ============================================================
template<bool REMAP>
__global__ __launch_bounds__(256) void sgemm128(
    const float* __restrict__ A, const float* __restrict__ Bm,
    const float* __restrict__ bias, float* __restrict__ C, int ldc)
{
    const int K = 1024;
    __shared__ float As[8][128];
    __shared__ float Bs[8][128];

    int tid = threadIdx.x;
    int tx  = tid & 15;
    int ty  = tid >> 4;
    int m0  = blockIdx.y * 128;
    int n0  = blockIdx.x * 128;

    float acc[8][8] = {};

    int a_row  = tid >> 1;
    int a_col4 = (tid & 1) * 4;
    int b_row  = tid >> 5;
    int b_col4 = (tid & 31) * 4;

    const float* Ag = A  + (size_t)(m0 + a_row) * K + a_col4;
    const float* Bg = Bm + (size_t)b_row * 1024 + n0 + b_col4;

    for (int k0 = 0; k0 < K; k0 += 8) {
        float4 av = *(const float4*)(Ag + k0);
        float4 bv = *(const float4*)(Bg + (size_t)k0 * 1024);
        __syncthreads();
        As[a_col4 + 0][a_row] = av.x;
        As[a_col4 + 1][a_row] = av.y;
        As[a_col4 + 2][a_row] = av.z;
        As[a_col4 + 3][a_row] = av.w;
        *(float4*)&Bs[b_row][b_col4] = bv;
        __syncthreads();

        #pragma unroll
        for (int kk = 0; kk < 8; kk++) {
            float af[8], bf[8];
            *(float4*)(af)     = *(const float4*)&As[kk][ty * 8];
            *(float4*)(af + 4) = *(const float4*)&As[kk][ty * 8 + 4];
            *(float4*)(bf)     = *(const float4*)&Bs[kk][tx * 8];
            *(float4*)(bf + 4) = *(const float4*)&Bs[kk][tx * 8 + 4];
            #pragma unroll
            for (int i = 0; i < 8; i++)
                #pragma unroll
                for (int j = 0; j < 8; j++)
                    acc[i][j] += af[i] * bf[j];
        }
    }

    #pragma unroll
    for (int i = 0; i < 8; i++) {
        int r = m0 + ty * 8 + i;
        size_t rowoff;
        if (REMAP) {
            int b = r >> 8;
            int t = r & 255;
            rowoff = ((size_t)t * B_ + b) * (size_t)ldc;
        } else {
            rowoff = (size_t)r * (size_t)ldc;
        }
        #pragma unroll
        for (int j = 0; j < 8; j += 4) {
            int col = n0 + tx * 8 + j;
            float4 v;
            v.x = acc[i][j + 0] + bias[col + 0];
            v.y = acc[i][j + 1] + bias[col + 1];
            v.z = acc[i][j + 2] + bias[col + 2];
            v.w = acc[i][j + 3] + bias[col + 3];
            *(float4*)(C + rowoff + col) = v;
        }
    }
}

// ============================================================
// grid barrier (all 128 blocks co-resident, 1/SM)
// ============================================================
__device__ __forceinline__ void grid_sync_128(int tid)
{
    __syncthreads();
    if (tid == 0) {
        unsigned gen = *(volatile unsigned*)&g_bar_gen;
        __threadfence();
        if (atomicAdd(&g_bar_count, 1u) == NBLK - 1) {
            g_bar_count = 0;
            __threadfence();
            atomicExch(&g_bar_gen, gen + 1u);
        } else {
            while (*(volatile unsigned*)&g_bar_gen == gen) { __nanosleep(64); }
            __threadfence();
        }
    }
    __syncthreads();
}

// ============================================================
// Persistent LSTM recurrence v2: 1 B/MAC smem traffic.
// 128 blocks x 256 threads. Block owns 8 h-cols (32 gate-cols), all 64 rows.
// Thread tile: 8 rows x 8 gate-cols x 128 k (8-way k-split via warp id).
//   kg = warp (tid>>5), rgrp = lane&7 (rows rgrp*8..+8),
//   cgrp = lane>>3 (gate-cols cgrp*8..+8).
// U smem-resident [k][32] (128 KB). h transposed per 128-k chunk,
// double-buffered [2][128][KST]. Partial-sum reduction through the
// (reused) h buffer. Cell state c lives in registers for all 256 steps.
// ============================================================
extern "C" __global__ void __launch_bounds__(256, 1) lstm_persistent(
    const float* __restrict__ Ui, const float* __restrict__ Uf,
    const float* __restrict__ Uj, const float* __restrict__ Uo)
{
    extern __shared__ float smem[];
    float* su  = smem;                       // [1024][32]  = 32768 floats (128KB)
    float* sht = smem + 32768;               // [2][128][KST] = 17408 floats (69.6KB)
    float* sred = sht;                       // reduction reuses sht (17408 >= 8*KGS)

    const int tid  = threadIdx.x;
    const int lane = tid & 31;
    const int kg   = tid >> 5;               // k-split group 0..7
    const int rgrp = lane & 7;               // row group
    const int cgrp = lane >> 3;              // gate-col group 0..3
    const int n0   = blockIdx.x * 8;

    // staging roles (independent of compute roles)
    const int s_row = (lane >> 2) + 8 * kg;  // 0..63
    const int s_kq0 = lane & 3;              // kq = s_kq0 + 4*i

    // epilogue roles
    const int e_row = tid >> 2;              // 0..63
    const int e_cp  = tid & 3;               // col pair
    const int e_nc  = n0 + 2 * e_cp;

    // ---- stage U once: su[k][gc] = U_{gc>>3}[k][n0 + (gc&7)] ----
    const float* Uptr[4] = {Ui, Uf, Uj, Uo};
    for (int i = 0; i < 128; i++) {
        int idx = i * 256 + tid;             // 0..32767
        int k   = idx >> 5;
        int gc  = idx & 31;
        su[idx] = Uptr[gc >> 3][(size_t)k * 1024 + n0 + (gc & 7)];
    }

    // ---- cell state in registers ----
    float2 creg = *(const float2*)(g_cbuf + e_row * H_ + e_nc);
    __syncthreads();

    for (int t = 0; t < T_; t++) {
        const float* hprev = g_hbuf[t & 1];
        float*       hnext = g_hbuf[(t + 1) & 1];

        // prefetch gx for this thread's 2 cells
        const float* gxp = g_gx + (size_t)t * B_ * G4 + (size_t)e_row * G4 + e_nc;
        float2 gxi = *(const float2*)(gxp);
        float2 gxf = *(const float2*)(gxp + 1024);
        float2 gxj = *(const float2*)(gxp + 2048);
        float2 gxo = *(const float2*)(gxp + 3072);

        float acc[8][8];
        #pragma unroll
        for (int i = 0; i < 8; i++)
            #pragma unroll
            for (int j = 0; j < 8; j++) acc[i][j] = 0.f;

        // ---- stage chunk 0 (transposed) ----
        float4 pf[8];
        #pragma unroll
        for (int i = 0; i < 8; i++) {
            int kq = s_kq0 + 4 * i;
            pf[i] = *(const float4*)(hprev + (size_t)s_row * H_ + kq * 4);
        }
        #pragma unroll
        for (int i = 0; i < 8; i++) {
            int kq = s_kq0 + 4 * i;
            float* d = sht + (kq * 4) * KST + s_row;
            d[0 * KST] = pf[i].x;
            d[1 * KST] = pf[i].y;
            d[2 * KST] = pf[i].z;
            d[3 * KST] = pf[i].w;
        }
        __syncthreads();

        for (int cch = 0; cch < 8; cch++) {
            // issue next-chunk global loads early
            if (cch < 7) {
                int k0 = (cch + 1) * 128;
                #pragma unroll
                for (int i = 0; i < 8; i++) {
                    int kq = s_kq0 + 4 * i;
                    pf[i] = *(const float4*)(hprev + (size_t)s_row * H_ + k0 + kq * 4);
                }
            }

            // compute this thread's 16-k slice of the chunk
            const float* shb = sht + (cch & 1) * (128 * KST)
                             + (kg * 16) * KST + rgrp * 8;
            const float* sup = su + (size_t)(cch * 128 + kg * 16) * 32 + cgrp * 8;
            #pragma unroll 8
            for (int kk = 0; kk < 16; kk++) {
                float hr[8], uc[8];
                *(float4*)(hr)     = *(const float4*)(shb + kk * KST);
                *(float4*)(hr + 4) = *(const float4*)(shb + kk * KST + 4);
                *(float4*)(uc)     = *(const float4*)(sup + kk * 32);
                *(float4*)(uc + 4) = *(const float4*)(sup + kk * 32 + 4);
                #pragma unroll
                for (int i = 0; i < 8; i++)
                    #pragma unroll
                    for (int j = 0; j < 8; j++)
                        acc[i][j] += hr[i] * uc[j];
            }

            // store next chunk into the other buffer
            if (cch < 7) {
                float* dst = sht + ((cch + 1) & 1) * (128 * KST);
                #pragma unroll
                for (int i = 0; i < 8; i++) {
                    int kq = s_kq0 + 4 * i;
                    float* d = dst + (kq * 4) * KST + s_row;
                    d[0 * KST] = pf[i].x;
                    d[1 * KST] = pf[i].y;
                    d[2 * KST] = pf[i].z;
                    d[3 * KST] = pf[i].w;
                }
            }
            __syncthreads();
        }

        // ---- write k-split partials (reuses sht region) ----
        #pragma unroll
        for (int r = 0; r < 8; r++) {
            int row = rgrp * 8 + r;
            float* base = sred + kg * KGS + row * RST + cgrp * 8;
            #pragma unroll
            for (int cp = 0; cp < 4; cp++)
                *(float2*)(base + 2 * cp) = make_float2(acc[r][2 * cp], acc[r][2 * cp + 1]);
        }
        __syncthreads();

        // ---- reduce over 8 kg + gate math for 2 cells ----
        float2 pg[4];
        #pragma unroll
        for (int g = 0; g < 4; g++) {
            float2 s = make_float2(0.f, 0.f);
            #pragma unroll
            for (int q = 0; q < 8; q++) {
                float2 v = *(const float2*)(sred + q * KGS + e_row * RST + g * 8 + 2 * e_cp);
                s.x += v.x; s.y += v.y;
            }
            pg[g] = s;
        }

        float2 hv;
        {
            float gi = pg[0].x + gxi.x, gf = pg[1].x + gxf.x;
            float gj = pg[2].x + gxj.x, go = pg[3].x + gxo.x;
            float iv = sigf(gi), fv = sigf(gf), jv = tanhfast(gj), ov = sigf(go);
            creg.x = fv * creg.x + iv * jv;
            hv.x = ov * tanhfast(creg.x);
        }
        {
            float gi = pg[0].y + gxi.y, gf = pg[1].y + gxf.y;
            float gj = pg[2].y + gxj.y, go = pg[3].y + gxo.y;
            float iv = sigf(gi), fv = sigf(gf), jv = tanhfast(gj), ov = sigf(go);
            creg.y = fv * creg.y + iv * jv;
            hv.y = ov * tanhfast(creg.y);
        }

        *(float2*)(hnext + e_row * H_ + e_nc) = hv;
        *(float2*)(g_hs + (size_t)e_row * T_ * H_ + (size_t)t * H_ + e_nc) = hv;

        grid_sync_128(tid);
    }
}

// ============================================================
// Inputs: x, h0, c0, W_i..W_o, U_i..U_o, b_i..b_o, W_y, b_y
// ============================================================
extern "C" void kernel_launch(void* const* d_in, const int* in_sizes, int n_in,
                              void* d_out, int out_size)
{
    const float* x  = (const float*)d_in[0];
    const float* h0 = (const float*)d_in[1];
    const float* c0 = (const float*)d_in[2];
    const float* W[4] = {(const float*)d_in[3], (const float*)d_in[4],
                         (const float*)d_in[5], (const float*)d_in[6]};
    const float* U[4] = {(const float*)d_in[7], (const float*)d_in[8],
                         (const float*)d_in[9], (const float*)d_in[10]};
    const float* bb[4] = {(const float*)d_in[11], (const float*)d_in[12],
                          (const float*)d_in[13], (const float*)d_in[14]};
    const float* Wy = (const float*)d_in[15];
    const float* by = (const float*)d_in[16];
    float* y = (float*)d_out;

    cudaMemcpyToSymbolAsync(g_hbuf, h0, (size_t)B_ * H_ * sizeof(float), 0,
                            cudaMemcpyDeviceToDevice, 0);
    cudaMemcpyToSymbolAsync(g_cbuf, c0, (size_t)B_ * H_ * sizeof(float), 0,
                            cudaMemcpyDeviceToDevice, 0);

    float* gx_ptr; cudaGetSymbolAddress((void**)&gx_ptr, g_gx);
    float* hs_ptr; cudaGetSymbolAddress((void**)&hs_ptr, g_hs);

    dim3 grid(8, 128);

    for (int g = 0; g < 4; g++)
        sgemm128<true><<<grid, 256>>>(x, W[g], bb[g], gx_ptr + g * 1024, G4);

    const int smem_bytes = (32768 + 2 * 128 * KST) * sizeof(float);  // 200.7 KB
    cudaFuncSetAttribute(lstm_persistent,
                         cudaFuncAttributeMaxDynamicSharedMemorySize, smem_bytes);
    lstm_persistent<<<NBLK, 256, smem_bytes>>>(U[0], U[1], U[2], U[3]);

    sgemm128<false><<<grid, 256>>>(hs_ptr, Wy, by, y, 1024);
}

// round 7
// speedup vs baseline: 3.3267x; 1.4200x over previous
#include <cuda_runtime.h>
#include <cuda_bf16.h>
#include <math.h>
#include <stdint.h>

#define B_  64
#define T_  256
#define D_  1024
#define H_  1024
#define G4  4096
#define NBLK 128
#define KST 68
#define RST 34
#define KGS 2176

#define KCAT 3072      // split-K: [hi | lo | hi] x [hi | hi | lo]
#define NCH  48        // KCAT / 64

// ---- scratch (device globals) ----
__device__ float g_gx[(size_t)T_ * B_ * G4];
__device__ float g_hs[(size_t)B_ * T_ * H_];
__device__ float g_hbuf[2][B_ * H_];
__device__ float g_cbuf[B_ * H_];
__device__ __nv_bfloat16 g_acat[(size_t)16384 * KCAT];
__device__ __nv_bfloat16 g_hcat[(size_t)16384 * KCAT];
__device__ __nv_bfloat16 g_bgx[(size_t)4096 * KCAT];
__device__ __nv_bfloat16 g_bwy[(size_t)1024 * KCAT];
__device__ float g_bcat[4096];

__device__ unsigned g_bar_count = 0;
__device__ unsigned g_bar_gen   = 0;

__device__ __forceinline__ float sigf(float x)    { return 1.f / (1.f + __expf(-x)); }
__device__ __forceinline__ float tanhfast(float x){ return 2.f * sigf(2.f * x) - 1.f; }

// ============================================================
// base-target PTX helpers (NO 'a'-suffix features)
// ============================================================
__device__ __forceinline__ uint32_t smem_u32(const void* p) {
    uint32_t a;
    asm("{ .reg .u64 t; cvta.to.shared.u64 t, %1; cvt.u32.u64 %0, t; }" : "=r"(a) : "l"(p));
    return a;
}
#define SWZ128(o) ((o) ^ (((o) >> 3) & 0x70))

__device__ __forceinline__ void cpasync16(uint32_t dst, const void* src) {
    asm volatile("cp.async.cg.shared.global [%0], [%1], 16;" :: "r"(dst), "l"(src));
}
#define CP_COMMIT() asm volatile("cp.async.commit_group;" ::: "memory")
#define CP_WAIT0()  asm volatile("cp.async.wait_group 0;" ::: "memory")
#define CP_WAIT1()  asm volatile("cp.async.wait_group 1;" ::: "memory")

__device__ __forceinline__ void ldsm4(uint32_t* r, uint32_t addr) {
    asm volatile("ldmatrix.sync.aligned.m8n8.x4.shared.b16 {%0,%1,%2,%3}, [%4];"
                 : "=r"(r[0]), "=r"(r[1]), "=r"(r[2]), "=r"(r[3]) : "r"(addr));
}
__device__ __forceinline__ void mma16816(float* d, const uint32_t* a, const uint32_t* b) {
    asm volatile(
        "mma.sync.aligned.m16n8k16.row.col.f32.bf16.bf16.f32 "
        "{%0,%1,%2,%3}, {%4,%5,%6,%7}, {%8,%9}, {%0,%1,%2,%3};"
        : "+f"(d[0]), "+f"(d[1]), "+f"(d[2]), "+f"(d[3])
        : "r"(a[0]), "r"(a[1]), "r"(a[2]), "r"(a[3]), "r"(b[0]), "r"(b[1]));
}

// ============================================================
// mma.sync bf16-split GEMM: C[M,N] = A[M,KCAT] @ B[N,KCAT]^T + bias
// CTA tile 128x128, 8 warps of 64x32, K chunks of 64, cp.async double buffer.
// smem: 2 * (16KB A + 16KB B) = 64 KB dynamic.
// ============================================================
template<bool REMAP>
__global__ void __launch_bounds__(256, 2) gemm_mma(
    const __nv_bfloat16* __restrict__ A, const __nv_bfloat16* __restrict__ Bm,
    const float* __restrict__ bias, float* __restrict__ C, int ldc)
{
    extern __shared__ char sm[];
    const uint32_t sb = smem_u32(sm);
    const int tid = threadIdx.x;
    const int wid = tid >> 5;
    const int lane = tid & 31;
    const int m0 = blockIdx.y * 128;
    const int n0 = blockIdx.x * 128;
    const int wm = (wid & 1) * 64;
    const int wn = (wid >> 1) * 32;

    const __nv_bfloat16* Ab = A + (size_t)m0 * KCAT;
    const __nv_bfloat16* Bb = Bm + (size_t)n0 * KCAT;

    // loader: one 64-k chunk (A 128x64, B 128x64) into buffer buf
    const int l_row = tid >> 3;          // 0..31 (+32*i)
    const int l_c16 = tid & 7;
    auto issue = [&](int buf, int kbase) {
        uint32_t ab = sb + buf * 32768;
        uint32_t bbs = ab + 16384;
        #pragma unroll
        for (int i = 0; i < 4; i++) {
            int row = l_row + i * 32;
            cpasync16(ab + SWZ128(row * 128 + l_c16 * 16),
                      Ab + (size_t)row * KCAT + kbase + l_c16 * 8);
        }
        #pragma unroll
        for (int i = 0; i < 4; i++) {
            int row = l_row + i * 32;
            cpasync16(bbs + SWZ128(row * 128 + l_c16 * 16),
                      Bb + (size_t)row * KCAT + kbase + l_c16 * 8);
        }
        CP_COMMIT();
    };

    float acc[4][4][4];
    #pragma unroll
    for (int i = 0; i < 4; i++)
        #pragma unroll
        for (int j = 0; j < 4; j++)
            #pragma unroll
            for (int q = 0; q < 4; q++) acc[i][j][q] = 0.f;

    // ldmatrix lane address components
    const int a_row = wm + (lane & 15);
    const int a_kb  = (lane >> 4) * 16;
    const int b_row = wn + ((lane >> 4) << 3) + (lane & 7);
    const int b_kb  = ((lane >> 3) & 1) * 16;

    issue(0, 0);

    for (int c = 0; c < NCH; c++) {
        if (c + 1 < NCH) { issue((c + 1) & 1, (c + 1) * 64); CP_WAIT1(); }
        else             { CP_WAIT0(); }
        __syncthreads();

        uint32_t ab = sb + (c & 1) * 32768;
        uint32_t bbs = ab + 16384;
        #pragma unroll
        for (int ks = 0; ks < 4; ks++) {
            uint32_t afr[4][4], bfr[2][4];
            #pragma unroll
            for (int mt = 0; mt < 4; mt++)
                ldsm4(afr[mt], ab + SWZ128((a_row + mt * 16) * 128 + ks * 32 + a_kb));
            #pragma unroll
            for (int np = 0; np < 2; np++)
                ldsm4(bfr[np], bbs + SWZ128((b_row + np * 16) * 128 + ks * 32 + b_kb));
            #pragma unroll
            for (int mt = 0; mt < 4; mt++) {
                mma16816(acc[mt][0], afr[mt], &bfr[0][0]);
                mma16816(acc[mt][1], afr[mt], &bfr[0][2]);
                mma16816(acc[mt][2], afr[mt], &bfr[1][0]);
                mma16816(acc[mt][3], afr[mt], &bfr[1][2]);
            }
        }
        __syncthreads();
    }

    // epilogue: fragment (row l/4 [+8], col (l&3)*2 [+1]) per 16x8 tile
    const int er = lane >> 2;
    const int ec = (lane & 3) * 2;
    #pragma unroll
    for (int mt = 0; mt < 4; mt++) {
        int r_lo = m0 + wm + mt * 16 + er;
        int r_hi = r_lo + 8;
        size_t off_lo, off_hi;
        if (REMAP) {  // r = b*256 + t  ->  gx row t*64 + b
            off_lo = ((size_t)(r_lo & 255) * 64 + (r_lo >> 8)) * (size_t)ldc;
            off_hi = ((size_t)(r_hi & 255) * 64 + (r_hi >> 8)) * (size_t)ldc;
        } else {
            off_lo = (size_t)r_lo * (size_t)ldc;
            off_hi = (size_t)r_hi * (size_t)ldc;
        }
        #pragma unroll
        for (int nt = 0; nt < 4; nt++) {
            int col = n0 + wn + nt * 8 + ec;
            float b0 = bias[col], b1 = bias[col + 1];
            float2 v0 = make_float2(acc[mt][nt][0] + b0, acc[mt][nt][1] + b1);
            float2 v1 = make_float2(acc[mt][nt][2] + b0, acc[mt][nt][3] + b1);
            *(float2*)(C + off_lo + col) = v0;
            *(float2*)(C + off_hi + col) = v1;
        }
    }
}

// ============================================================
// prep kernels
// ============================================================
__device__ __forceinline__ void split_bf(float x, __nv_bfloat16& h, __nv_bfloat16& l) {
    h = __float2bfloat16(x);
    l = __float2bfloat16(x - __bfloat162float(h));
}

__global__ void __launch_bounds__(256) prep_split(
    const float* __restrict__ src, __nv_bfloat16* __restrict__ dst)
{
    int t = blockIdx.x * 256 + threadIdx.x;
    int r = t >> 8, q = t & 255;
    float4 v = *(const float4*)(src + (size_t)r * 1024 + q * 4);
    __nv_bfloat16 h[4], l[4];
    split_bf(v.x, h[0], l[0]); split_bf(v.y, h[1], l[1]);
    split_bf(v.z, h[2], l[2]); split_bf(v.w, h[3], l[3]);
    __nv_bfloat16* d = dst + (size_t)r * KCAT;
    __nv_bfloat162 hp0 = {h[0], h[1]}, hp1 = {h[2], h[3]};
    __nv_bfloat162 lp0 = {l[0], l[1]}, lp1 = {l[2], l[3]};
    *(__nv_bfloat162*)(d + q * 4)         = hp0;
    *(__nv_bfloat162*)(d + q * 4 + 2)     = hp1;
    *(__nv_bfloat162*)(d + 1024 + q * 4)     = lp0;
    *(__nv_bfloat162*)(d + 1024 + q * 4 + 2) = lp1;
    *(__nv_bfloat162*)(d + 2048 + q * 4)     = hp0;
    *(__nv_bfloat162*)(d + 2048 + q * 4 + 2) = hp1;
}

__global__ void __launch_bounds__(256) prep_wsplit(
    const float* __restrict__ W0, const float* __restrict__ W1,
    const float* __restrict__ W2, const float* __restrict__ W3,
    __nv_bfloat16* __restrict__ dst)
{
    int t = blockIdx.x * 256 + threadIdx.x;
    int n = t / 768;
    int k4 = (t - n * 768) * 4;
    int band = k4 >> 10;
    int kk = k4 & 1023;
    int g = n >> 10, c = n & 1023;
    const float* W = (g == 0) ? W0 : (g == 1) ? W1 : (g == 2) ? W2 : W3;
    __nv_bfloat16 o[4];
    #pragma unroll
    for (int j = 0; j < 4; j++) {
        float w = __ldg(W + (size_t)(kk + j) * 1024 + c);
        __nv_bfloat16 h, l;
        split_bf(w, h, l);
        o[j] = (band < 2) ? h : l;
    }
    __nv_bfloat16* d = dst + (size_t)n * KCAT + k4;
    *(__nv_bfloat162*)(d)     = {o[0], o[1]};
    *(__nv_bfloat162*)(d + 2) = {o[2], o[3]};
}

__global__ void __launch_bounds__(256) prep_bias(
    const float* __restrict__ b0, const float* __restrict__ b1,
    const float* __restrict__ b2, const float* __restrict__ b3)
{
    int n = blockIdx.x * 256 + threadIdx.x;
    int g = n >> 10, c = n & 1023;
    const float* b = (g == 0) ? b0 : (g == 1) ? b1 : (g == 2) ? b2 : b3;
    g_bcat[n] = b[c];
}

// ============================================================
// grid barrier + persistent recurrence (unchanged from R4)
// ============================================================
__device__ __forceinline__ void grid_sync_128(int tid)
{
    __syncthreads();
    if (tid == 0) {
        unsigned gen = *(volatile unsigned*)&g_bar_gen;
        __threadfence();
        if (atomicAdd(&g_bar_count, 1u) == NBLK - 1) {
            g_bar_count = 0;
            __threadfence();
            atomicExch(&g_bar_gen, gen + 1u);
        } else {
            while (*(volatile unsigned*)&g_bar_gen == gen) { __nanosleep(64); }
            __threadfence();
        }
    }
    __syncthreads();
}

extern "C" __global__ void __launch_bounds__(256, 1) lstm_persistent(
    const float* __restrict__ Ui, const float* __restrict__ Uf,
    const float* __restrict__ Uj, const float* __restrict__ Uo)
{
    extern __shared__ float smemf[];
    float* su  = smemf;
    float* sht = smemf + 32768;
    float* sred = sht;

    const int tid  = threadIdx.x;
    const int lane = tid & 31;
    const int kg   = tid >> 5;
    const int rgrp = lane & 7;
    const int cgrp = lane >> 3;
    const int n0   = blockIdx.x * 8;

    const int s_row = (lane >> 2) + 8 * kg;
    const int s_kq0 = lane & 3;

    const int e_row = tid >> 2;
    const int e_cp  = tid & 3;
    const int e_nc  = n0 + 2 * e_cp;

    const float* Uptr[4] = {Ui, Uf, Uj, Uo};
    for (int i = 0; i < 128; i++) {
        int idx = i * 256 + tid;
        int k   = idx >> 5;
        int gc  = idx & 31;
        su[idx] = Uptr[gc >> 3][(size_t)k * 1024 + n0 + (gc & 7)];
    }

    float2 creg = *(const float2*)(g_cbuf + e_row * H_ + e_nc);
    __syncthreads();

    for (int t = 0; t < T_; t++) {
        const float* hprev = g_hbuf[t & 1];
        float*       hnext = g_hbuf[(t + 1) & 1];

        const float* gxp = g_gx + (size_t)t * B_ * G4 + (size_t)e_row * G4 + e_nc;
        float2 gxi = *(const float2*)(gxp);
        float2 gxf = *(const float2*)(gxp + 1024);
        float2 gxj = *(const float2*)(gxp + 2048);
        float2 gxo = *(const float2*)(gxp + 3072);

        float acc[8][8];
        #pragma unroll
        for (int i = 0; i < 8; i++)
            #pragma unroll
            for (int j = 0; j < 8; j++) acc[i][j] = 0.f;

        float4 pf[8];
        #pragma unroll
        for (int i = 0; i < 8; i++) {
            int kq = s_kq0 + 4 * i;
            pf[i] = *(const float4*)(hprev + (size_t)s_row * H_ + kq * 4);
        }
        #pragma unroll
        for (int i = 0; i < 8; i++) {
            int kq = s_kq0 + 4 * i;
            float* d = sht + (kq * 4) * KST + s_row;
            d[0 * KST] = pf[i].x;
            d[1 * KST] = pf[i].y;
            d[2 * KST] = pf[i].z;
            d[3 * KST] = pf[i].w;
        }
        __syncthreads();

        for (int cch = 0; cch < 8; cch++) {
            if (cch < 7) {
                int k0 = (cch + 1) * 128;
                #pragma unroll
                for (int i = 0; i < 8; i++) {
                    int kq = s_kq0 + 4 * i;
                    pf[i] = *(const float4*)(hprev + (size_t)s_row * H_ + k0 + kq * 4);
                }
            }

            const float* shb = sht + (cch & 1) * (128 * KST)
                             + (kg * 16) * KST + rgrp * 8;
            const float* sup = su + (size_t)(cch * 128 + kg * 16) * 32 + cgrp * 8;
            #pragma unroll 8
            for (int kk = 0; kk < 16; kk++) {
                float hr[8], uc[8];
                *(float4*)(hr)     = *(const float4*)(shb + kk * KST);
                *(float4*)(hr + 4) = *(const float4*)(shb + kk * KST + 4);
                *(float4*)(uc)     = *(const float4*)(sup + kk * 32);
                *(float4*)(uc + 4) = *(const float4*)(sup + kk * 32 + 4);
                #pragma unroll
                for (int i = 0; i < 8; i++)
                    #pragma unroll
                    for (int j = 0; j < 8; j++)
                        acc[i][j] += hr[i] * uc[j];
            }

            if (cch < 7) {
                float* dst = sht + ((cch + 1) & 1) * (128 * KST);
                #pragma unroll
                for (int i = 0; i < 8; i++) {
                    int kq = s_kq0 + 4 * i;
                    float* d = dst + (kq * 4) * KST + s_row;
                    d[0 * KST] = pf[i].x;
                    d[1 * KST] = pf[i].y;
                    d[2 * KST] = pf[i].z;
                    d[3 * KST] = pf[i].w;
                }
            }
            __syncthreads();
        }

        #pragma unroll
        for (int r = 0; r < 8; r++) {
            int row = rgrp * 8 + r;
            float* base = sred + kg * KGS + row * RST + cgrp * 8;
            #pragma unroll
            for (int cp = 0; cp < 4; cp++)
                *(float2*)(base + 2 * cp) = make_float2(acc[r][2 * cp], acc[r][2 * cp + 1]);
        }
        __syncthreads();

        float2 pg[4];
        #pragma unroll
        for (int g = 0; g < 4; g++) {
            float2 s = make_float2(0.f, 0.f);
            #pragma unroll
            for (int q = 0; q < 8; q++) {
                float2 v = *(const float2*)(sred + q * KGS + e_row * RST + g * 8 + 2 * e_cp);
                s.x += v.x; s.y += v.y;
            }
            pg[g] = s;
        }

        float2 hv;
        {
            float gi = pg[0].x + gxi.x, gf = pg[1].x + gxf.x;
            float gj = pg[2].x + gxj.x, go = pg[3].x + gxo.x;
            float iv = sigf(gi), fv = sigf(gf), jv = tanhfast(gj), ov = sigf(go);
            creg.x = fv * creg.x + iv * jv;
            hv.x = ov * tanhfast(creg.x);
        }
        {
            float gi = pg[0].y + gxi.y, gf = pg[1].y + gxf.y;
            float gj = pg[2].y + gxj.y, go = pg[3].y + gxo.y;
            float iv = sigf(gi), fv = sigf(gf), jv = tanhfast(gj), ov = sigf(go);
            creg.y = fv * creg.y + iv * jv;
            hv.y = ov * tanhfast(creg.y);
        }

        *(float2*)(hnext + e_row * H_ + e_nc) = hv;
        *(float2*)(g_hs + (size_t)e_row * T_ * H_ + (size_t)t * H_ + e_nc) = hv;

        grid_sync_128(tid);
    }
}

// ============================================================
// Inputs: x, h0, c0, W_i..W_o, U_i..U_o, b_i..b_o, W_y, b_y
// ============================================================
extern "C" void kernel_launch(void* const* d_in, const int* in_sizes, int n_in,
                              void* d_out, int out_size)
{
    const float* x  = (const float*)d_in[0];
    const float* h0 = (const float*)d_in[1];
    const float* c0 = (const float*)d_in[2];
    const float* W[4] = {(const float*)d_in[3], (const float*)d_in[4],
                         (const float*)d_in[5], (const float*)d_in[6]};
    const float* U[4] = {(const float*)d_in[7], (const float*)d_in[8],
                         (const float*)d_in[9], (const float*)d_in[10]};
    const float* bb[4] = {(const float*)d_in[11], (const float*)d_in[12],
                          (const float*)d_in[13], (const float*)d_in[14]};
    const float* Wy = (const float*)d_in[15];
    const float* by = (const float*)d_in[16];
    float* y = (float*)d_out;

    cudaMemcpyToSymbolAsync(g_hbuf, h0, (size_t)B_ * H_ * sizeof(float), 0,
                            cudaMemcpyDeviceToDevice, 0);
    cudaMemcpyToSymbolAsync(g_cbuf, c0, (size_t)B_ * H_ * sizeof(float), 0,
                            cudaMemcpyDeviceToDevice, 0);

    float* gx_ptr; cudaGetSymbolAddress((void**)&gx_ptr, g_gx);
    float* hs_ptr; cudaGetSymbolAddress((void**)&hs_ptr, g_hs);
    __nv_bfloat16* acat; cudaGetSymbolAddress((void**)&acat, g_acat);
    __nv_bfloat16* hcat; cudaGetSymbolAddress((void**)&hcat, g_hcat);
    __nv_bfloat16* bgx;  cudaGetSymbolAddress((void**)&bgx,  g_bgx);
    __nv_bfloat16* bwy;  cudaGetSymbolAddress((void**)&bwy,  g_bwy);
    float* bcat; cudaGetSymbolAddress((void**)&bcat, g_bcat);

    const int gemm_smem = 65536;
    cudaFuncSetAttribute(gemm_mma<true>,
                         cudaFuncAttributeMaxDynamicSharedMemorySize, gemm_smem);
    cudaFuncSetAttribute(gemm_mma<false>,
                         cudaFuncAttributeMaxDynamicSharedMemorySize, gemm_smem);

    // prep: split x, W (4 gates), biases
    prep_split<<<16384, 256>>>(x, acat);
    prep_wsplit<<<12288, 256>>>(W[0], W[1], W[2], W[3], bgx);
    prep_wsplit<<<3072, 256>>>(Wy, Wy, Wy, Wy, bwy);
    prep_bias<<<16, 256>>>(bb[0], bb[1], bb[2], bb[3]);

    // gx = x @ [W_i|W_f|W_j|W_o] + b  (HMMA, REMAP into [T][B][4H])
    gemm_mma<true><<<dim3(G4 / 128, 16384 / 128), 256, gemm_smem>>>(
        acat, bgx, bcat, gx_ptr, G4);

    // persistent recurrence
    const int smem_rec = (32768 + 2 * 128 * KST) * sizeof(float);
    cudaFuncSetAttribute(lstm_persistent,
                         cudaFuncAttributeMaxDynamicSharedMemorySize, smem_rec);
    lstm_persistent<<<NBLK, 256, smem_rec>>>(U[0], U[1], U[2], U[3]);

    // y = hs @ W_y + b_y
    prep_split<<<16384, 256>>>(hs_ptr, hcat);
    gemm_mma<false><<<dim3(1024 / 128, 16384 / 128), 256, gemm_smem>>>(
        hcat, bwy, by, y, 1024);
}

// round 9
// speedup vs baseline: 6.3268x; 1.9018x over previous
#include <cuda_runtime.h>
#include <cuda_bf16.h>
#include <math.h>
#include <stdint.h>

#define B_  64
#define T_  256
#define H_  1024
#define G4  4096
#define NBLK 128

#define KCAT 3072      // split-K: [hi | lo | hi] x [hi | hi | lo]
#define NCH  48        // KCAT / 64

// ---- scratch (device globals) ----
__device__ float g_gx[(size_t)T_ * B_ * G4];
__device__ __nv_bfloat16 g_acat[(size_t)16384 * KCAT];
__device__ __nv_bfloat16 g_hcat[(size_t)16384 * KCAT];   // written by recurrence epilogue
__device__ __nv_bfloat16 g_h0cat[64 * 2048];             // h0 split [row][hi 1024 | lo 1024]
__device__ __nv_bfloat16 g_bgx[(size_t)4096 * KCAT];
__device__ __nv_bfloat16 g_bwy[(size_t)1024 * KCAT];
__device__ float g_bcat[4096];

__device__ unsigned g_bar_count = 0;
__device__ unsigned g_bar_gen   = 0;

__device__ __forceinline__ float sigf(float x)    { return 1.f / (1.f + __expf(-x)); }
__device__ __forceinline__ float tanhfast(float x){ return 2.f * sigf(2.f * x) - 1.f; }

// ============================================================
// base-target PTX helpers
// ============================================================
__device__ __forceinline__ uint32_t smem_u32(const void* p) {
    uint32_t a;
    asm("{ .reg .u64 t; cvta.to.shared.u64 t, %1; cvt.u32.u64 %0, t; }" : "=r"(a) : "l"(p));
    return a;
}
#define SWZ128(o) ((o) ^ (((o) >> 3) & 0x70))

__device__ __forceinline__ void cpasync16(uint32_t dst, const void* src) {
    asm volatile("cp.async.cg.shared.global [%0], [%1], 16;" :: "r"(dst), "l"(src));
}
#define CP_COMMIT() asm volatile("cp.async.commit_group;" ::: "memory")
#define CP_WAIT0()  asm volatile("cp.async.wait_group 0;" ::: "memory")
#define CP_WAIT1()  asm volatile("cp.async.wait_group 1;" ::: "memory")

__device__ __forceinline__ void ldsm4(uint32_t* r, uint32_t addr) {
    asm volatile("ldmatrix.sync.aligned.m8n8.x4.shared.b16 {%0,%1,%2,%3}, [%4];"
                 : "=r"(r[0]), "=r"(r[1]), "=r"(r[2]), "=r"(r[3]) : "r"(addr));
}
__device__ __forceinline__ void mma16816(float* d, const uint32_t* a, const uint32_t* b) {
    asm volatile(
        "mma.sync.aligned.m16n8k16.row.col.f32.bf16.bf16.f32 "
        "{%0,%1,%2,%3}, {%4,%5,%6,%7}, {%8,%9}, {%0,%1,%2,%3};"
        : "+f"(d[0]), "+f"(d[1]), "+f"(d[2]), "+f"(d[3])
        : "r"(a[0]), "r"(a[1]), "r"(a[2]), "r"(a[3]), "r"(b[0]), "r"(b[1]));
}
__device__ __forceinline__ void split_bf(float x, __nv_bfloat16& h, __nv_bfloat16& l) {
    h = __float2bfloat16(x);
    l = __float2bfloat16(x - __bfloat162float(h));
}

// ============================================================
// mma.sync bf16-split GEMM (unchanged, proven in R7)
// ============================================================
template<bool REMAP>
__global__ void __launch_bounds__(256, 2) gemm_mma(
    const __nv_bfloat16* __restrict__ A, const __nv_bfloat16* __restrict__ Bm,
    const float* __restrict__ bias, float* __restrict__ C, int ldc)
{
    extern __shared__ char sm[];
    const uint32_t sb = smem_u32(sm);
    const int tid = threadIdx.x;
    const int wid = tid >> 5;
    const int lane = tid & 31;
    const int m0 = blockIdx.y * 128;
    const int n0 = blockIdx.x * 128;
    const int wm = (wid & 1) * 64;
    const int wn = (wid >> 1) * 32;

    const __nv_bfloat16* Ab = A + (size_t)m0 * KCAT;
    const __nv_bfloat16* Bb = Bm + (size_t)n0 * KCAT;

    const int l_row = tid >> 3;
    const int l_c16 = tid & 7;
    auto issue = [&](int buf, int kbase) {
        uint32_t ab = sb + buf * 32768;
        uint32_t bbs = ab + 16384;
        #pragma unroll
        for (int i = 0; i < 4; i++) {
            int row = l_row + i * 32;
            cpasync16(ab + SWZ128(row * 128 + l_c16 * 16),
                      Ab + (size_t)row * KCAT + kbase + l_c16 * 8);
        }
        #pragma unroll
        for (int i = 0; i < 4; i++) {
            int row = l_row + i * 32;
            cpasync16(bbs + SWZ128(row * 128 + l_c16 * 16),
                      Bb + (size_t)row * KCAT + kbase + l_c16 * 8);
        }
        CP_COMMIT();
    };

    float acc[4][4][4];
    #pragma unroll
    for (int i = 0; i < 4; i++)
        #pragma unroll
        for (int j = 0; j < 4; j++)
            #pragma unroll
            for (int q = 0; q < 4; q++) acc[i][j][q] = 0.f;

    const int a_row = wm + (lane & 15);
    const int a_kb  = (lane >> 4) * 16;
    const int b_row = wn + ((lane >> 4) << 3) + (lane & 7);
    const int b_kb  = ((lane >> 3) & 1) * 16;

    issue(0, 0);

    for (int c = 0; c < NCH; c++) {
        if (c + 1 < NCH) { issue((c + 1) & 1, (c + 1) * 64); CP_WAIT1(); }
        else             { CP_WAIT0(); }
        __syncthreads();

        uint32_t ab = sb + (c & 1) * 32768;
        uint32_t bbs = ab + 16384;
        #pragma unroll
        for (int ks = 0; ks < 4; ks++) {
            uint32_t afr[4][4], bfr[2][4];
            #pragma unroll
            for (int mt = 0; mt < 4; mt++)
                ldsm4(afr[mt], ab + SWZ128((a_row + mt * 16) * 128 + ks * 32 + a_kb));
            #pragma unroll
            for (int np = 0; np < 2; np++)
                ldsm4(bfr[np], bbs + SWZ128((b_row + np * 16) * 128 + ks * 32 + b_kb));
            #pragma unroll
            for (int mt = 0; mt < 4; mt++) {
                mma16816(acc[mt][0], afr[mt], &bfr[0][0]);
                mma16816(acc[mt][1], afr[mt], &bfr[0][2]);
                mma16816(acc[mt][2], afr[mt], &bfr[1][0]);
                mma16816(acc[mt][3], afr[mt], &bfr[1][2]);
            }
        }
        __syncthreads();
    }

    const int er = lane >> 2;
    const int ec = (lane & 3) * 2;
    #pragma unroll
    for (int mt = 0; mt < 4; mt++) {
        int r_lo = m0 + wm + mt * 16 + er;
        int r_hi = r_lo + 8;
        size_t off_lo, off_hi;
        if (REMAP) {
            off_lo = ((size_t)(r_lo & 255) * 64 + (r_lo >> 8)) * (size_t)ldc;
            off_hi = ((size_t)(r_hi & 255) * 64 + (r_hi >> 8)) * (size_t)ldc;
        } else {
            off_lo = (size_t)r_lo * (size_t)ldc;
            off_hi = (size_t)r_hi * (size_t)ldc;
        }
        #pragma unroll
        for (int nt = 0; nt < 4; nt++) {
            int col = n0 + wn + nt * 8 + ec;
            float b0 = bias[col], b1 = bias[col + 1];
            *(float2*)(C + off_lo + col) = make_float2(acc[mt][nt][0] + b0, acc[mt][nt][1] + b1);
            *(float2*)(C + off_hi + col) = make_float2(acc[mt][nt][2] + b0, acc[mt][nt][3] + b1);
        }
    }
}

// ============================================================
// prep kernels
// ============================================================
__global__ void __launch_bounds__(256) prep_split(
    const float* __restrict__ src, __nv_bfloat16* __restrict__ dst)
{
    int t = blockIdx.x * 256 + threadIdx.x;
    int r = t >> 8, q = t & 255;
    float4 v = *(const float4*)(src + (size_t)r * 1024 + q * 4);
    __nv_bfloat16 h[4], l[4];
    split_bf(v.x, h[0], l[0]); split_bf(v.y, h[1], l[1]);
    split_bf(v.z, h[2], l[2]); split_bf(v.w, h[3], l[3]);
    __nv_bfloat16* d = dst + (size_t)r * KCAT;
    __nv_bfloat162 hp0 = {h[0], h[1]}, hp1 = {h[2], h[3]};
    __nv_bfloat162 lp0 = {l[0], l[1]}, lp1 = {l[2], l[3]};
    *(__nv_bfloat162*)(d + q * 4)         = hp0;
    *(__nv_bfloat162*)(d + q * 4 + 2)     = hp1;
    *(__nv_bfloat162*)(d + 1024 + q * 4)     = lp0;
    *(__nv_bfloat162*)(d + 1024 + q * 4 + 2) = lp1;
    *(__nv_bfloat162*)(d + 2048 + q * 4)     = hp0;
    *(__nv_bfloat162*)(d + 2048 + q * 4 + 2) = hp1;
}

__global__ void __launch_bounds__(256) prep_wsplit(
    const float* __restrict__ W0, const float* __restrict__ W1,
    const float* __restrict__ W2, const float* __restrict__ W3,
    __nv_bfloat16* __restrict__ dst)
{
    int t = blockIdx.x * 256 + threadIdx.x;
    int n = t / 768;
    int k4 = (t - n * 768) * 4;
    int band = k4 >> 10;
    int kk = k4 & 1023;
    int g = n >> 10, c = n & 1023;
    const float* W = (g == 0) ? W0 : (g == 1) ? W1 : (g == 2) ? W2 : W3;
    __nv_bfloat16 o[4];
    #pragma unroll
    for (int j = 0; j < 4; j++) {
        float w = __ldg(W + (size_t)(kk + j) * 1024 + c);
        __nv_bfloat16 h, l;
        split_bf(w, h, l);
        o[j] = (band < 2) ? h : l;
    }
    __nv_bfloat16* d = dst + (size_t)n * KCAT + k4;
    *(__nv_bfloat162*)(d)     = {o[0], o[1]};
    *(__nv_bfloat162*)(d + 2) = {o[2], o[3]};
}

__global__ void __launch_bounds__(256) prep_bias(
    const float* __restrict__ b0, const float* __restrict__ b1,
    const float* __restrict__ b2, const float* __restrict__ b3)
{
    int n = blockIdx.x * 256 + threadIdx.x;
    int g = n >> 10, c = n & 1023;
    const float* b = (g == 0) ? b0 : (g == 1) ? b1 : (g == 2) ? b2 : b3;
    g_bcat[n] = b[c];
}

__global__ void __launch_bounds__(256) prep_h0(const float* __restrict__ h0)
{
    int row = blockIdx.x;
    #pragma unroll
    for (int i = 0; i < 4; i++) {
        int k = i * 256 + threadIdx.x;
        float v = h0[row * 1024 + k];
        __nv_bfloat16 hi, lo;
        split_bf(v, hi, lo);
        g_h0cat[row * 2048 + k]        = hi;
        g_h0cat[row * 2048 + 1024 + k] = lo;
    }
}

// ============================================================
// grid barrier
// ============================================================
__device__ __forceinline__ void grid_sync_128(int tid)
{
    __syncthreads();
    if (tid == 0) {
        unsigned gen = *(volatile unsigned*)&g_bar_gen;
        __threadfence();
        if (atomicAdd(&g_bar_count, 1u) == NBLK - 1) {
            g_bar_count = 0;
            __threadfence();
            atomicExch(&g_bar_gen, gen + 1u);
        } else {
            while (*(volatile unsigned*)&g_bar_gen == gen) { __nanosleep(64); }
            __threadfence();
        }
    }
    __syncthreads();
}

// ============================================================
// Tensorized persistent LSTM recurrence.
// 128 blocks x 256 threads (8 warps). Block owns 8 hidden cols (32 gate-cols).
// U split hi/lo staged ONCE in smem (128 KB, n-major SW128, ldmatrix layout).
// Per step: h (bf16 hi/lo from g_hcat / g_h0cat) streamed in 128-k chunks,
// double-buffered cp.async. Warp tile 16m x 16n (2 gates); per 16-k:
// 4 ldsm4 + 6 HMMA (3 error terms x 2 n-tiles). Gate recombine via smem
// exchange; cell state in registers; epilogue writes h as [hi|lo|hi] bands
// straight into g_hcat (the y-GEMM input layout).
// smem: U 128K + h 2x32K = 192 KB.
// ============================================================
#define RSM_ULO 65536
#define RSM_H   131072
#define RSM_HBUF 32768
#define RSM_TOTAL 196608

extern "C" __global__ void __launch_bounds__(256, 1) lstm_mma(
    const float* __restrict__ Ui, const float* __restrict__ Uf,
    const float* __restrict__ Uj, const float* __restrict__ Uo,
    const float* __restrict__ c0)
{
    extern __shared__ char sm[];
    const uint32_t sb = smem_u32(sm);
    const int tid  = threadIdx.x;
    const int lane = tid & 31;
    const int w    = tid >> 5;
    const int wm   = (w & 3) * 16;   // batch rows wm..wm+15
    const int gh   = w >> 2;         // gate half: 0 -> {i,f}, 1 -> {j,o}
    const int n0   = blockIdx.x * 8;

    // ---- stage U hi/lo once: region layout [k64-chunk][nrow][64k] SW128 ----
    const float* Uptr[4] = {Ui, Uf, Uj, Uo};
    for (int it = 0; it < 128; it++) {
        int idx = it * 256 + tid;            // 0..32767 = (k, nrow)
        int k = idx >> 5, nrow = idx & 31;   // nrow = g*8 + c
        int g = nrow >> 3, c = nrow & 7;
        float v = __ldg(Uptr[g] + (size_t)k * 1024 + n0 + c);
        __nv_bfloat16 hi, lo;
        split_bf(v, hi, lo);
        uint32_t off = (k >> 6) * 4096 + SWZ128(nrow * 128 + (k & 63) * 2);
        *(__nv_bfloat16*)(sm + off)           = hi;
        *(__nv_bfloat16*)(sm + RSM_ULO + off) = lo;
    }

    // ---- cell-state ownership (fixed across steps) ----
    const int e_row = tid >> 2;              // batch row 0..63
    const int e_c2  = (tid & 3) * 2;         // 2 hidden cols
    float2 creg = *(const float2*)(c0 + e_row * H_ + n0 + e_c2);
    __syncthreads();

    // fragment lane addressing (R7-proven pattern)
    const int a_row = wm + (lane & 15);
    const int a_kb  = (lane >> 4) * 16;
    const int b_row = gh * 16 + ((lane >> 4) << 3) + (lane & 7);
    const int b_kb  = ((lane >> 3) & 1) * 16;
    const int er = lane >> 2;
    const int ec = (lane & 3) * 2;

    float* sgf = (float*)(sm + RSM_H);       // gate exchange [64][34] (reuses h buf0)

    for (int t = 0; t < T_; t++) {
        // h source for this step
        const __nv_bfloat16* hbase;
        size_t rstr;
        if (t == 0) { hbase = g_h0cat;                       rstr = 2048;  }
        else        { hbase = g_hcat + (size_t)(t - 1) * KCAT; rstr = 256 * (size_t)KCAT; }

        auto issue = [&](int bf, int cc) {
            uint32_t hb = sb + RSM_H + bf * RSM_HBUF;
            int kbase = cc * 128;
            #pragma unroll
            for (int i = 0; i < 8; i++) {
                int u = i * 256 + tid;
                int half = u >> 10, rem = u & 1023;
                int row = rem >> 4, seg = rem & 15;
                const __nv_bfloat16* src =
                    hbase + (size_t)row * rstr + half * 1024 + kbase + seg * 8;
                uint32_t dst = hb + half * 16384 + (seg >> 3) * 8192
                             + SWZ128(row * 128 + (seg & 7) * 16);
                cpasync16(dst, src);
            }
            CP_COMMIT();
        };

        // prefetch gx for this thread's 2 cells
        const float* gxp = g_gx + ((size_t)t * 64 + e_row) * G4 + n0 + e_c2;
        float2 gxi = *(const float2*)(gxp);
        float2 gxf = *(const float2*)(gxp + 1024);
        float2 gxj = *(const float2*)(gxp + 2048);
        float2 gxo = *(const float2*)(gxp + 3072);

        float acc[2][4];
        #pragma unroll
        for (int i = 0; i < 2; i++)
            #pragma unroll
            for (int q = 0; q < 4; q++) acc[i][q] = 0.f;

        issue(0, 0);

        for (int cc = 0; cc < 8; cc++) {
            if (cc < 7) { issue((cc + 1) & 1, cc + 1); CP_WAIT1(); }
            else        { CP_WAIT0(); }
            __syncthreads();

            uint32_t hb = sb + RSM_H + (cc & 1) * RSM_HBUF;
            #pragma unroll
            for (int ks = 0; ks < 8; ks++) {
                int sub = ks >> 2, ks4 = ks & 3;
                uint32_t a_off = sub * 8192 + SWZ128(a_row * 128 + ks4 * 32 + a_kb);
                uint32_t ahi[4], alo[4], bhi[4], blo[4];
                ldsm4(ahi, hb + a_off);
                ldsm4(alo, hb + 16384 + a_off);
                uint32_t b_off = (cc * 2 + sub) * 4096
                               + SWZ128(b_row * 128 + ks4 * 32 + b_kb);
                ldsm4(bhi, sb + b_off);
                ldsm4(blo, sb + RSM_ULO + b_off);
                mma16816(acc[0], ahi, &bhi[0]);
                mma16816(acc[1], ahi, &bhi[2]);
                mma16816(acc[0], alo, &bhi[0]);
                mma16816(acc[1], alo, &bhi[2]);
                mma16816(acc[0], ahi, &blo[0]);
                mma16816(acc[1], ahi, &blo[2]);
            }
            __syncthreads();
        }

        // ---- gate exchange (reuses h buf0 region; buf0 idle after chunk 6) ----
        #pragma unroll
        for (int nt = 0; nt < 2; nt++) {
            int g = gh * 2 + nt;
            sgf[(wm + er) * 34 + g * 8 + ec]         = acc[nt][0];
            sgf[(wm + er) * 34 + g * 8 + ec + 1]     = acc[nt][1];
            sgf[(wm + er + 8) * 34 + g * 8 + ec]     = acc[nt][2];
            sgf[(wm + er + 8) * 34 + g * 8 + ec + 1] = acc[nt][3];
        }
        __syncthreads();

        float2 pg[4];
        #pragma unroll
        for (int g = 0; g < 4; g++)
            pg[g] = *(const float2*)&sgf[e_row * 34 + g * 8 + e_c2];

        float2 hv;
        {
            float gi = pg[0].x + gxi.x, gf = pg[1].x + gxf.x;
            float gj = pg[2].x + gxj.x, go = pg[3].x + gxo.x;
            float iv = sigf(gi), fv = sigf(gf), jv = tanhfast(gj), ov = sigf(go);
            creg.x = fv * creg.x + iv * jv;
            hv.x = ov * tanhfast(creg.x);
        }
        {
            float gi = pg[0].y + gxi.y, gf = pg[1].y + gxf.y;
            float gj = pg[2].y + gxj.y, go = pg[3].y + gxo.y;
            float iv = sigf(gi), fv = sigf(gf), jv = tanhfast(gj), ov = sigf(go);
            creg.y = fv * creg.y + iv * jv;
            hv.y = ov * tanhfast(creg.y);
        }

        // write h split straight into g_hcat [hi | lo | hi] (y-GEMM layout)
        {
            __nv_bfloat16 hx, lx, hy, ly;
            split_bf(hv.x, hx, lx);
            split_bf(hv.y, hy, ly);
            __nv_bfloat16* d = g_hcat + ((size_t)e_row * 256 + t) * KCAT + n0 + e_c2;
            __nv_bfloat162 hp = {hx, hy}, lp = {lx, ly};
            *(__nv_bfloat162*)(d)        = hp;
            *(__nv_bfloat162*)(d + 1024) = lp;
            *(__nv_bfloat162*)(d + 2048) = hp;
        }

        grid_sync_128(tid);
    }
}

// ============================================================
// Inputs: x, h0, c0, W_i..W_o, U_i..U_o, b_i..b_o, W_y, b_y
// ============================================================
extern "C" void kernel_launch(void* const* d_in, const int* in_sizes, int n_in,
                              void* d_out, int out_size)
{
    const float* x  = (const float*)d_in[0];
    const float* h0 = (const float*)d_in[1];
    const float* c0 = (const float*)d_in[2];
    const float* W[4] = {(const float*)d_in[3], (const float*)d_in[4],
                         (const float*)d_in[5], (const float*)d_in[6]};
    const float* U[4] = {(const float*)d_in[7], (const float*)d_in[8],
                         (const float*)d_in[9], (const float*)d_in[10]};
    const float* bb[4] = {(const float*)d_in[11], (const float*)d_in[12],
                          (const float*)d_in[13], (const float*)d_in[14]};
    const float* Wy = (const float*)d_in[15];
    const float* by = (const float*)d_in[16];
    float* y = (float*)d_out;

    float* gx_ptr; cudaGetSymbolAddress((void**)&gx_ptr, g_gx);
    __nv_bfloat16* acat; cudaGetSymbolAddress((void**)&acat, g_acat);
    __nv_bfloat16* hcat; cudaGetSymbolAddress((void**)&hcat, g_hcat);
    __nv_bfloat16* bgx;  cudaGetSymbolAddress((void**)&bgx,  g_bgx);
    __nv_bfloat16* bwy;  cudaGetSymbolAddress((void**)&bwy,  g_bwy);
    float* bcat; cudaGetSymbolAddress((void**)&bcat, g_bcat);

    const int gemm_smem = 65536;
    cudaFuncSetAttribute(gemm_mma<true>,
                         cudaFuncAttributeMaxDynamicSharedMemorySize, gemm_smem);
    cudaFuncSetAttribute(gemm_mma<false>,
                         cudaFuncAttributeMaxDynamicSharedMemorySize, gemm_smem);
    cudaFuncSetAttribute(lstm_mma,
                         cudaFuncAttributeMaxDynamicSharedMemorySize, RSM_TOTAL);

    // prep
    prep_split<<<16384, 256>>>(x, acat);
    prep_wsplit<<<12288, 256>>>(W[0], W[1], W[2], W[3], bgx);
    prep_wsplit<<<3072, 256>>>(Wy, Wy, Wy, Wy, bwy);
    prep_bias<<<16, 256>>>(bb[0], bb[1], bb[2], bb[3]);
    prep_h0<<<64, 256>>>(h0);

    // gx = x @ [W_i|W_f|W_j|W_o] + b  (REMAP into [T][B][4H])
    gemm_mma<true><<<dim3(G4 / 128, 16384 / 128), 256, gemm_smem>>>(
        acat, bgx, bcat, gx_ptr, G4);

    // tensorized persistent recurrence (writes g_hcat directly)
    lstm_mma<<<NBLK, 256, RSM_TOTAL>>>(U[0], U[1], U[2], U[3], c0);

    // y = hs @ W_y + b_y
    gemm_mma<false><<<dim3(1024 / 128, 16384 / 128), 256, gemm_smem>>>(
        hcat, bwy, by, y, 1024);
}